// round 4
// baseline (speedup 1.0000x reference)
#include <cuda_runtime.h>
#include <cstdint>

// Problem sizes (fixed by the reference)
#define NNODES 50000
#define NREL   8
#define DIM    128
#define NEDGE  800000
#define NTRIP  100000
#define KTOT   1152          // NREL*DIM + DIM (root folded as 9th block)
#define K0LIM  1024          // NREL*DIM

// ---------------- scratch (static device globals; no allocs allowed) -------
__device__ __align__(16) float g_sum[(size_t)NNODES * NREL * DIM]; // 204.8 MB
__device__ __align__(16) float g_cnt[(size_t)NNODES * NREL];       // 1.6 MB
__device__ __align__(16) float g_h1[(size_t)NNODES * DIM];         // 25.6 MB
__device__ __align__(16) float g_h2[(size_t)NNODES * DIM];         // 25.6 MB

// ---------------- zero scratch --------------------------------------------
__global__ void zero_kernel(int zeroCnt) {
    const size_t n4 = (size_t)NNODES * NREL * DIM / 4;
    float4 z = make_float4(0.f, 0.f, 0.f, 0.f);
    float4* p = reinterpret_cast<float4*>(g_sum);
    for (size_t i = (size_t)blockIdx.x * blockDim.x + threadIdx.x;
         i < n4; i += (size_t)gridDim.x * blockDim.x)
        p[i] = z;
    if (zeroCnt) {
        const size_t c4 = (size_t)NNODES * NREL / 4;
        float4* q = reinterpret_cast<float4*>(g_cnt);
        for (size_t i = (size_t)blockIdx.x * blockDim.x + threadIdx.x;
             i < c4; i += (size_t)gridDim.x * blockDim.x)
            q[i] = z;
    }
}

// ---------------- edge scatter: one warp per edge -------------------------
// h[src] (512B row) gathered as float4 per lane, reduced into g_sum[(dst*R+et)]
__global__ void scatter_kernel(const float* __restrict__ h_ext, int useG,
                               const int* __restrict__ ei,
                               const int* __restrict__ et,
                               int addCnt) {
    int gw   = (blockIdx.x * blockDim.x + threadIdx.x) >> 5;
    int lane = threadIdx.x & 31;
    if (gw >= NEDGE) return;
    const float* __restrict__ h = useG ? g_h1 : h_ext;

    int src = ei[gw];
    int dst = ei[NEDGE + gw];
    int r   = et[gw];

    float4 v = reinterpret_cast<const float4*>(h + (size_t)src * DIM)[lane];
    float* p = g_sum + ((size_t)dst * NREL + r) * DIM + lane * 4;
    asm volatile("red.global.add.v4.f32 [%0], {%1,%2,%3,%4};"
                 :: "l"(p), "f"(v.x), "f"(v.y), "f"(v.z), "f"(v.w)
                 : "memory");
    if (addCnt && lane == 0)
        atomicAdd(g_cnt + (size_t)dst * NREL + r, 1.0f);
}

// ---------------- fused RGCN layer GEMM -----------------------------------
// out[n,:] = relu( sum_{r,d} (g_sum[n,r,d]/max(cnt,1)) * W[r*128+d,:]
//                 + sum_d hin[n,d]*root[d,:] + bias )
// GEMM (50000 x 1152) @ (1152 x 128), BM=64 BN=128 BK=32, 256 thr, 4x8 tile.
#define BM 64
#define BN 128
#define BK 32
#define BMP 68

__global__ __launch_bounds__(256) void rgcn_gemm_kernel(
    const float* __restrict__ hin_ext, int useGin,
    const float* __restrict__ W,      // (1024,128) = W_l flattened
    const float* __restrict__ root,   // (128,128)
    const float* __restrict__ bias,   // (128)
    int outSel)                       // 0 -> g_h1, 1 -> g_h2
{
    __shared__ float sA[BK][BMP];   // A tile, transposed [k][m]
    __shared__ float sB[BK][BN];    // W tile [k][h]
    __shared__ float sInv[BM][NREL];

    const float* __restrict__ hin = useGin ? g_h1 : hin_ext;
    float* __restrict__ hout = outSel ? g_h2 : g_h1;

    const int tid  = threadIdx.x;
    const int row0 = blockIdx.x * BM;
    const int tx   = tid & 15;   // output col group (8 cols)
    const int ty   = tid >> 4;   // output row group (4 rows)

    // per-(row, rel) 1/max(cnt,1)
    for (int i = tid; i < BM * NREL; i += 256) {
        int m = i >> 3, r = i & 7;
        int n = row0 + m;
        float c = (n < NNODES) ? g_cnt[(size_t)n * NREL + r] : 1.0f;
        sInv[m][r] = 1.0f / fmaxf(c, 1.0f);
    }

    float acc[4][8];
#pragma unroll
    for (int i = 0; i < 4; ++i)
#pragma unroll
        for (int j = 0; j < 8; ++j) acc[i][j] = 0.f;

    for (int k0 = 0; k0 < KTOT; k0 += BK) {
        __syncthreads();   // sA/sB reuse (and sInv on first iter)

        // ---- load A tile: 64 rows x 32 k, scale by 1/cnt ----
#pragma unroll
        for (int it = 0; it < 2; ++it) {
            int lin = tid + it * 256;
            int m   = lin >> 3;        // 0..63
            int kq  = lin & 7;         // float4 index within BK
            int n   = row0 + m;
            int k   = k0 + kq * 4;
            float4 v = make_float4(0.f, 0.f, 0.f, 0.f);
            if (n < NNODES) {
                if (k0 < K0LIM) {
                    v = *reinterpret_cast<const float4*>(
                        g_sum + (size_t)n * K0LIM + k);
                    float s = sInv[m][k >> 7];
                    v.x *= s; v.y *= s; v.z *= s; v.w *= s;
                } else {
                    v = *reinterpret_cast<const float4*>(
                        hin + (size_t)n * DIM + (k - K0LIM));
                }
            }
            int kk = kq * 4;
            sA[kk + 0][m] = v.x; sA[kk + 1][m] = v.y;
            sA[kk + 2][m] = v.z; sA[kk + 3][m] = v.w;
        }

        // ---- load B tile: 32 k x 128 h ----
        const float* Wsrc = (k0 < K0LIM) ? (W + (size_t)k0 * BN)
                                         : (root + (size_t)(k0 - K0LIM) * BN);
#pragma unroll
        for (int it = 0; it < 4; ++it) {
            int lin = tid + it * 256;
            int k   = lin >> 5;        // 0..31
            int hq  = lin & 31;        // float4 index over 128
            float4 v = *reinterpret_cast<const float4*>(
                Wsrc + (size_t)k * BN + hq * 4);
            *reinterpret_cast<float4*>(&sB[k][hq * 4]) = v;
        }
        __syncthreads();

        // ---- FMA: 4x8 register tile ----
#pragma unroll
        for (int kk = 0; kk < BK; ++kk) {
            float4 av = *reinterpret_cast<const float4*>(&sA[kk][ty * 4]);
            float4 b0 = *reinterpret_cast<const float4*>(&sB[kk][tx * 8]);
            float4 b1 = *reinterpret_cast<const float4*>(&sB[kk][tx * 8 + 4]);
            float a[4] = {av.x, av.y, av.z, av.w};
            float b[8] = {b0.x, b0.y, b0.z, b0.w, b1.x, b1.y, b1.z, b1.w};
#pragma unroll
            for (int i = 0; i < 4; ++i)
#pragma unroll
                for (int j = 0; j < 8; ++j)
                    acc[i][j] += a[i] * b[j];
        }
    }

    // ---- epilogue: bias + relu ----
    float bb[8];
#pragma unroll
    for (int j = 0; j < 8; ++j) bb[j] = bias[tx * 8 + j];
#pragma unroll
    for (int i = 0; i < 4; ++i) {
        int n = row0 + ty * 4 + i;
        if (n < NNODES) {
            float4 o0, o1;
            o0.x = fmaxf(acc[i][0] + bb[0], 0.f);
            o0.y = fmaxf(acc[i][1] + bb[1], 0.f);
            o0.z = fmaxf(acc[i][2] + bb[2], 0.f);
            o0.w = fmaxf(acc[i][3] + bb[3], 0.f);
            o1.x = fmaxf(acc[i][4] + bb[4], 0.f);
            o1.y = fmaxf(acc[i][5] + bb[5], 0.f);
            o1.z = fmaxf(acc[i][6] + bb[6], 0.f);
            o1.w = fmaxf(acc[i][7] + bb[7], 0.f);
            float* dst = hout + (size_t)n * DIM + tx * 8;
            *reinterpret_cast<float4*>(dst)     = o0;
            *reinterpret_cast<float4*>(dst + 4) = o1;
        }
    }
}

// ---------------- DistMult score: one warp per triple ---------------------
__global__ void score_kernel(const float* __restrict__ rel_emb,
                             const int* __restrict__ head,
                             const int* __restrict__ rel,
                             const int* __restrict__ tail,
                             float* __restrict__ out) {
    int t    = (blockIdx.x * blockDim.x + threadIdx.x) >> 5;
    int lane = threadIdx.x & 31;
    if (t >= NTRIP) return;
    const float4 a = reinterpret_cast<const float4*>(
        g_h2 + (size_t)head[t] * DIM)[lane];
    const float4 r = reinterpret_cast<const float4*>(
        rel_emb + (size_t)rel[t] * DIM)[lane];
    const float4 b = reinterpret_cast<const float4*>(
        g_h2 + (size_t)tail[t] * DIM)[lane];
    float s = a.x * r.x * b.x + a.y * r.y * b.y
            + a.z * r.z * b.z + a.w * r.w * b.w;
#pragma unroll
    for (int off = 16; off; off >>= 1)
        s += __shfl_xor_sync(0xFFFFFFFFu, s, off);
    if (lane == 0) out[t] = s;
}

// ---------------- launcher -------------------------------------------------
extern "C" void kernel_launch(void* const* d_in, const int* in_sizes, int n_in,
                              void* d_out, int out_size) {
    const float* emb   = (const float*)d_in[0];
    const float* W0    = (const float*)d_in[1];
    const float* root0 = (const float*)d_in[2];
    const float* b0    = (const float*)d_in[3];
    const float* W1    = (const float*)d_in[4];
    const float* root1 = (const float*)d_in[5];
    const float* b1    = (const float*)d_in[6];
    const float* relE  = (const float*)d_in[7];
    const int*   ei    = (const int*)d_in[8];
    const int*   et    = (const int*)d_in[9];
    const int*   hidx  = (const int*)d_in[10];
    const int*   ridx  = (const int*)d_in[11];
    const int*   tidx  = (const int*)d_in[12];
    float*       out   = (float*)d_out;

    const int zeroGrid    = 4096;
    const int scatterGrid = (NEDGE * 32 + 255) / 256;       // 100000
    const int gemmGrid    = (NNODES + BM - 1) / BM;         // 782
    const int scoreGrid   = (NTRIP * 32 + 255) / 256;       // 12500

    // ----- layer 0 -----
    zero_kernel<<<zeroGrid, 256>>>(1);
    scatter_kernel<<<scatterGrid, 256>>>(emb, 0, ei, et, 1);
    rgcn_gemm_kernel<<<gemmGrid, 256>>>(emb, 0, W0, root0, b0, /*outSel=*/0);

    // ----- layer 1 (counts unchanged; zero only sums) -----
    zero_kernel<<<zeroGrid, 256>>>(0);
    scatter_kernel<<<scatterGrid, 256>>>(nullptr, 1, ei, et, 0);
    rgcn_gemm_kernel<<<gemmGrid, 256>>>(nullptr, 1, W1, root1, b1, /*outSel=*/1);

    // ----- DistMult score -----
    score_kernel<<<scoreGrid, 256>>>(relE, hidx, ridx, tidx, out);
}

// round 6
// speedup vs baseline: 2.7345x; 2.7345x over previous
#include <cuda_runtime.h>
#include <cstdint>

// Problem sizes (fixed by the reference)
#define NNODES 50000
#define NREL   8
#define DIM    128
#define NEDGE  800000
#define NTRIP  100000
#define KTOT   1152          // NREL*DIM + DIM (root folded as 9th block)
#define K0LIM  1024          // NREL*DIM

// ---------------- scratch (static device globals; no allocs allowed) -------
__device__ __align__(16) float g_sum[(size_t)NNODES * NREL * DIM]; // 204.8 MB
__device__ __align__(16) float g_cnt[(size_t)NNODES * NREL];       // 1.6 MB
__device__ __align__(16) float g_h1[(size_t)NNODES * DIM];         // 25.6 MB
__device__ __align__(16) float g_h2[(size_t)NNODES * DIM];         // 25.6 MB
__device__ __align__(16) float g_WT0[(size_t)DIM * KTOT];          // (W0||root0)^T, tf32-rounded
__device__ __align__(16) float g_WT1[(size_t)DIM * KTOT];          // (W1||root1)^T, tf32-rounded

// ---------------- zero scratch --------------------------------------------
__global__ void zero_kernel(int zeroCnt) {
    const size_t n4 = (size_t)NNODES * NREL * DIM / 4;
    float4 z = make_float4(0.f, 0.f, 0.f, 0.f);
    float4* p = reinterpret_cast<float4*>(g_sum);
    for (size_t i = (size_t)blockIdx.x * blockDim.x + threadIdx.x;
         i < n4; i += (size_t)gridDim.x * blockDim.x)
        p[i] = z;
    if (zeroCnt) {
        const size_t c4 = (size_t)NNODES * NREL / 4;
        float4* q = reinterpret_cast<float4*>(g_cnt);
        for (size_t i = (size_t)blockIdx.x * blockDim.x + threadIdx.x;
             i < c4; i += (size_t)gridDim.x * blockDim.x)
            q[i] = z;
    }
}

// ---------------- W||root transpose + tf32 round --------------------------
__global__ void transpose_w(const float* __restrict__ W0,
                            const float* __restrict__ root0,
                            const float* __restrict__ W1,
                            const float* __restrict__ root1) {
    int b = blockIdx.x;
    int layer = b / KTOT;
    int k = b % KTOT;
    const float* src;
    if (layer == 0)
        src = (k < K0LIM) ? (W0 + (size_t)k * DIM) : (root0 + (size_t)(k - K0LIM) * DIM);
    else
        src = (k < K0LIM) ? (W1 + (size_t)k * DIM) : (root1 + (size_t)(k - K0LIM) * DIM);
    float v = src[threadIdx.x];
    uint32_t t;
    asm("cvt.rna.tf32.f32 %0, %1;" : "=r"(t) : "f"(v));
    float* dst = layer ? g_WT1 : g_WT0;
    dst[(size_t)threadIdx.x * KTOT + k] = __uint_as_float(t);
}

// ---------------- edge scatter: one warp per edge -------------------------
__global__ void scatter_kernel(const float* __restrict__ h_ext, int useG,
                               const int* __restrict__ ei,
                               const int* __restrict__ et,
                               int addCnt) {
    int gw   = (blockIdx.x * blockDim.x + threadIdx.x) >> 5;
    int lane = threadIdx.x & 31;
    if (gw >= NEDGE) return;
    const float* __restrict__ h = useG ? g_h1 : h_ext;

    int src = ei[gw];
    int dst = ei[NEDGE + gw];
    int r   = et[gw];

    float4 v = reinterpret_cast<const float4*>(h + (size_t)src * DIM)[lane];
    float* p = g_sum + ((size_t)dst * NREL + r) * DIM + lane * 4;
    asm volatile("red.global.add.v4.f32 [%0], {%1,%2,%3,%4};"
                 :: "l"(p), "f"(v.x), "f"(v.y), "f"(v.z), "f"(v.w)
                 : "memory");
    if (addCnt && lane == 0)
        atomicAdd(g_cnt + (size_t)dst * NREL + r, 1.0f);
}

// ---------------- tf32 mma.sync RGCN layer GEMM ---------------------------
// out[n,:] = relu( [g_sum[n,:]/cnt || hin[n,:]] @ Wcat + bias )
// Per CTA: BM=128, BN=128, BK=32. 8 warps (4x2), warp tile 32x64, m16n8k8.
#define KCH     32
#define NCHUNK  (KTOT / KCH)            // 36
#define LDP     36                      // padded smem row stride (floats)
// dynamic smem: sInv (1024 f) + 2 buffers x (A 128*36 + B 128*36)
#define SM_INV_F   0
#define SM_BUF_F   1024
#define BUF_F      (2 * 128 * LDP)      // 9216 floats per buffer (A+B)
#define SMEM_TOT   ((SM_BUF_F + 2 * BUF_F) * 4)   // 77824 B

__device__ __forceinline__ void mma_tf32(float* c, const uint32_t* a,
                                         const uint32_t* b) {
    asm volatile(
        "mma.sync.aligned.m16n8k8.row.col.f32.tf32.tf32.f32 "
        "{%0,%1,%2,%3}, {%4,%5,%6,%7}, {%8,%9}, {%0,%1,%2,%3};"
        : "+f"(c[0]), "+f"(c[1]), "+f"(c[2]), "+f"(c[3])
        : "r"(a[0]), "r"(a[1]), "r"(a[2]), "r"(a[3]), "r"(b[0]), "r"(b[1]));
}

__global__ __launch_bounds__(256) void rgcn_gemm_mma(
    const float* __restrict__ hin_ext, int useGin, int wtSel,
    const float* __restrict__ bias, int outSel)
{
    extern __shared__ float smemf[];
    const int tid  = threadIdx.x;
    const int wid  = tid >> 5;
    const int lane = tid & 31;
    const int g    = lane >> 2;      // group id (0..7)
    const int t4   = lane & 3;       // thread in group
    const int wr   = wid & 3;        // warp row  (M: 4 x 32)
    const int wc   = wid >> 2;       // warp col  (N: 2 x 64)
    const int row0 = blockIdx.x * 128;

    const float* __restrict__ hin  = useGin ? g_h1 : hin_ext;
    const float* __restrict__ WT   = wtSel ? g_WT1 : g_WT0;
    float* __restrict__ hout = outSel ? g_h2 : g_h1;
    float* sInv = smemf + SM_INV_F;

    // 1/max(cnt,1) per (row, rel)
    for (int i = tid; i < 128 * NREL; i += 256) {
        int m = i >> 3, r = i & 7;
        int n = row0 + m;
        float c = (n < NNODES) ? g_cnt[(size_t)n * NREL + r] : 1.0f;
        sInv[i] = 1.0f / fmaxf(c, 1.0f);
    }

    float acc[2][8][4];
#pragma unroll
    for (int mt = 0; mt < 2; ++mt)
#pragma unroll
        for (int nt = 0; nt < 8; ++nt)
#pragma unroll
            for (int j = 0; j < 4; ++j) acc[mt][nt][j] = 0.f;

    float4 va[4], vb[4];

    // ---- staged load: gmem -> regs for chunk c ----
    auto load_regs = [&](int c) {
        const int k0 = c * KCH;
#pragma unroll
        for (int it = 0; it < 4; ++it) {
            int idx = tid + it * 256;
            int m = idx >> 3, q = idx & 7;
            int n = row0 + m;
            float4 v = make_float4(0.f, 0.f, 0.f, 0.f);
            if (n < NNODES) {
                if (k0 < K0LIM)
                    v = *reinterpret_cast<const float4*>(
                        g_sum + (size_t)n * K0LIM + k0 + q * 4);
                else
                    v = *reinterpret_cast<const float4*>(
                        hin + (size_t)n * DIM + (k0 - K0LIM) + q * 4);
            }
            va[it] = v;
            vb[it] = *reinterpret_cast<const float4*>(
                WT + (size_t)m * KTOT + k0 + q * 4);
        }
    };

    // ---- store staged regs -> smem buffer (scale + tf32 round for A) ----
    auto store_smem = [&](int buf, int c) {
        const int k0 = c * KCH;
        float* smA = smemf + SM_BUF_F + buf * BUF_F;
        float* smB = smA + 128 * LDP;
#pragma unroll
        for (int it = 0; it < 4; ++it) {
            int idx = tid + it * 256;
            int m = idx >> 3, q = idx & 7;
            float4 v = va[it];
            if (k0 < K0LIM) {
                float s = sInv[m * 8 + (k0 >> 7)];
                v.x *= s; v.y *= s; v.z *= s; v.w *= s;
            }
            uint4 r;
            asm("cvt.rna.tf32.f32 %0, %1;" : "=r"(r.x) : "f"(v.x));
            asm("cvt.rna.tf32.f32 %0, %1;" : "=r"(r.y) : "f"(v.y));
            asm("cvt.rna.tf32.f32 %0, %1;" : "=r"(r.z) : "f"(v.z));
            asm("cvt.rna.tf32.f32 %0, %1;" : "=r"(r.w) : "f"(v.w));
            *reinterpret_cast<uint4*>(smA + m * LDP + q * 4) = r;
            *reinterpret_cast<float4*>(smB + m * LDP + q * 4) = vb[it];
        }
    };

    // ---- compute one k-chunk from smem buffer ----
    auto compute = [&](int buf) {
        const float* smA = smemf + SM_BUF_F + buf * BUF_F;
        const float* smB = smA + 128 * LDP;
#pragma unroll
        for (int ks = 0; ks < 4; ++ks) {
            const int kk = ks * 8;
            uint32_t a[2][4], b[8][2];
#pragma unroll
            for (int mt = 0; mt < 2; ++mt) {
                int r0 = wr * 32 + mt * 16 + g;
                a[mt][0] = __float_as_uint(smA[(r0)     * LDP + kk + t4]);
                a[mt][1] = __float_as_uint(smA[(r0 + 8) * LDP + kk + t4]);
                a[mt][2] = __float_as_uint(smA[(r0)     * LDP + kk + t4 + 4]);
                a[mt][3] = __float_as_uint(smA[(r0 + 8) * LDP + kk + t4 + 4]);
            }
#pragma unroll
            for (int nt = 0; nt < 8; ++nt) {
                int nn = wc * 64 + nt * 8 + g;
                b[nt][0] = __float_as_uint(smB[nn * LDP + kk + t4]);
                b[nt][1] = __float_as_uint(smB[nn * LDP + kk + t4 + 4]);
            }
#pragma unroll
            for (int mt = 0; mt < 2; ++mt)
#pragma unroll
                for (int nt = 0; nt < 8; ++nt)
                    mma_tf32(acc[mt][nt], a[mt], b[nt]);
        }
    };

    // ---- software pipeline: double buffer, one sync per chunk ----
    load_regs(0);
    store_smem(0, 0);
    __syncthreads();
    for (int c = 0; c < NCHUNK; ++c) {
        if (c + 1 < NCHUNK) load_regs(c + 1);
        compute(c & 1);
        if (c + 1 < NCHUNK) store_smem((c + 1) & 1, c + 1);
        __syncthreads();
    }

    // ---- epilogue: bias + relu, direct from accumulators ----
    float2 bb[8];
#pragma unroll
    for (int nt = 0; nt < 8; ++nt) {
        int col = wc * 64 + nt * 8 + t4 * 2;
        bb[nt].x = __ldg(bias + col);
        bb[nt].y = __ldg(bias + col + 1);
    }
#pragma unroll
    for (int mt = 0; mt < 2; ++mt) {
        int r0 = row0 + wr * 32 + mt * 16 + g;
#pragma unroll
        for (int half = 0; half < 2; ++half) {
            int n = r0 + half * 8;
            if (n < NNODES) {
                float* dst = hout + (size_t)n * DIM;
#pragma unroll
                for (int nt = 0; nt < 8; ++nt) {
                    int col = wc * 64 + nt * 8 + t4 * 2;
                    float2 o;
                    o.x = fmaxf(acc[mt][nt][half * 2 + 0] + bb[nt].x, 0.f);
                    o.y = fmaxf(acc[mt][nt][half * 2 + 1] + bb[nt].y, 0.f);
                    *reinterpret_cast<float2*>(dst + col) = o;
                }
            }
        }
    }
}

// ---------------- DistMult score: one warp per triple ---------------------
__global__ void score_kernel(const float* __restrict__ rel_emb,
                             const int* __restrict__ head,
                             const int* __restrict__ rel,
                             const int* __restrict__ tail,
                             float* __restrict__ out) {
    int t    = (blockIdx.x * blockDim.x + threadIdx.x) >> 5;
    int lane = threadIdx.x & 31;
    if (t >= NTRIP) return;
    const float4 a = reinterpret_cast<const float4*>(
        g_h2 + (size_t)head[t] * DIM)[lane];
    const float4 r = reinterpret_cast<const float4*>(
        rel_emb + (size_t)rel[t] * DIM)[lane];
    const float4 b = reinterpret_cast<const float4*>(
        g_h2 + (size_t)tail[t] * DIM)[lane];
    float s = a.x * r.x * b.x + a.y * r.y * b.y
            + a.z * r.z * b.z + a.w * r.w * b.w;
#pragma unroll
    for (int off = 16; off; off >>= 1)
        s += __shfl_xor_sync(0xFFFFFFFFu, s, off);
    if (lane == 0) out[t] = s;
}

// ---------------- launcher -------------------------------------------------
extern "C" void kernel_launch(void* const* d_in, const int* in_sizes, int n_in,
                              void* d_out, int out_size) {
    const float* emb   = (const float*)d_in[0];
    const float* W0    = (const float*)d_in[1];
    const float* root0 = (const float*)d_in[2];
    const float* b0    = (const float*)d_in[3];
    const float* W1    = (const float*)d_in[4];
    const float* root1 = (const float*)d_in[5];
    const float* b1    = (const float*)d_in[6];
    const float* relE  = (const float*)d_in[7];
    const int*   ei    = (const int*)d_in[8];
    const int*   et    = (const int*)d_in[9];
    const int*   hidx  = (const int*)d_in[10];
    const int*   ridx  = (const int*)d_in[11];
    const int*   tidx  = (const int*)d_in[12];
    float*       out   = (float*)d_out;

    static int smemSet = 0;
    if (!smemSet) {
        cudaFuncSetAttribute(rgcn_gemm_mma,
                             cudaFuncAttributeMaxDynamicSharedMemorySize,
                             SMEM_TOT);
        smemSet = 1;
    }

    const int zeroGrid    = 4096;
    const int scatterGrid = (NEDGE * 32 + 255) / 256;       // 100000
    const int gemmGrid    = (NNODES + 127) / 128;           // 391
    const int scoreGrid   = (NTRIP * 32 + 255) / 256;       // 12500

    // weights transpose + tf32 round (once, both layers)
    transpose_w<<<2 * KTOT, 128>>>(W0, root0, W1, root1);

    // ----- layer 0 -----
    zero_kernel<<<zeroGrid, 256>>>(1);
    scatter_kernel<<<scatterGrid, 256>>>(emb, 0, ei, et, 1);
    rgcn_gemm_mma<<<gemmGrid, 256, SMEM_TOT>>>(emb, 0, /*wtSel=*/0, b0, /*outSel=*/0);

    // ----- layer 1 (counts unchanged; zero only sums) -----
    zero_kernel<<<zeroGrid, 256>>>(0);
    scatter_kernel<<<scatterGrid, 256>>>(nullptr, 1, ei, et, 0);
    rgcn_gemm_mma<<<gemmGrid, 256, SMEM_TOT>>>(nullptr, 1, /*wtSel=*/1, b1, /*outSel=*/1);

    // ----- DistMult score -----
    score_kernel<<<scoreGrid, 256>>>(relE, hidx, ridx, tidx, out);
}